// round 11
// baseline (speedup 1.0000x reference)
#include <cuda_runtime.h>
#include <cuda_bf16.h>
#include <cstdint>

#define NPIX   262144
#define CD     256
#define HW     16384
#define TILE_P 64
#define NTILES (NPIX / TILE_P)      // 4096
#define GRID   148
#define NTHR   512
#define INV_T  14.285714285714285f

// smem layout (bytes)
#define B_STRIDE 528                  // 132 words = 4 mod 32 banks: conflict-free ldsm
#define A_STRIDE 144                  // 36 words  = 4 mod 32 banks
#define A_BUF    (256 * A_STRIDE)     // 36864
#define OFF_B    0
#define OFF_A    (256 * B_STRIDE)     // 135168
#define OFF_LAB  (OFF_A + 2 * A_BUF)  // 208896 : 2 x (64 px * 32 bytes)
#define SMEM_SZ  (OFF_LAB + 2 * 2048) // 212992

#define FIN_BLKS 512

__device__ float g_en[NTILES * 512];     // [tile][wn 0..7][row 0..63]  8MB
__device__ float g_ep[NTILES * 512];     // 8MB
__device__ float g_partial[FIN_BLKS];
__device__ int   g_pcnt[FIN_BLKS];

__device__ __forceinline__ uint32_t smem_u32(const void* p) {
    uint32_t a;
    asm("{ .reg .u64 t; cvta.to.shared.u64 t, %1; cvt.u32.u64 %0, t; }" : "=r"(a) : "l"(p));
    return a;
}
__device__ __forceinline__ void ldsm_x4(uint32_t* r, uint32_t addr) {
    asm volatile("ldmatrix.sync.aligned.m8n8.x4.shared.b16 {%0,%1,%2,%3}, [%4];"
                 : "=r"(r[0]), "=r"(r[1]), "=r"(r[2]), "=r"(r[3]) : "r"(addr));
}
__device__ __forceinline__ void ldsm_x4_t(uint32_t* r, uint32_t addr) {
    asm volatile("ldmatrix.sync.aligned.m8n8.x4.trans.shared.b16 {%0,%1,%2,%3}, [%4];"
                 : "=r"(r[0]), "=r"(r[1]), "=r"(r[2]), "=r"(r[3]) : "r"(addr));
}
__device__ __forceinline__ void mma_bf16(float* d, const uint32_t* a,
                                         uint32_t b0, uint32_t b1) {
    asm volatile(
        "mma.sync.aligned.m16n8k16.row.col.f32.bf16.bf16.f32 "
        "{%0,%1,%2,%3}, {%4,%5,%6,%7}, {%8,%9}, {%0,%1,%2,%3};"
        : "+f"(d[0]), "+f"(d[1]), "+f"(d[2]), "+f"(d[3])
        : "r"(a[0]), "r"(a[1]), "r"(a[2]), "r"(a[3]), "r"(b0), "r"(b1));
}
__device__ __forceinline__ unsigned mask8(const int4& v0, const int4& v1) {
    unsigned m = 0;
    m |= (v0.x != 0 ? 1u : 0u);
    m |= (v0.y != 0 ? 2u : 0u);
    m |= (v0.z != 0 ? 4u : 0u);
    m |= (v0.w != 0 ? 8u : 0u);
    m |= (v1.x != 0 ? 16u : 0u);
    m |= (v1.y != 0 ? 32u : 0u);
    m |= (v1.z != 0 ? 64u : 0u);
    m |= (v1.w != 0 ? 128u : 0u);
    return m;
}

// fragment set for one kstep
struct Frag { uint32_t a[2][4]; uint32_t b[2][4]; };

__device__ __forceinline__ void load_frag(Frag& f, uint32_t a_base, uint32_t b_base,
                                          int ks) {
    ldsm_x4_t(f.a[0], a_base + (uint32_t)ks * 16 * A_STRIDE);
    ldsm_x4_t(f.a[1], a_base + (uint32_t)ks * 16 * A_STRIDE + 32);
    ldsm_x4(f.b[0], b_base + (uint32_t)ks * 32);
    ldsm_x4(f.b[1], b_base + 16 * B_STRIDE + (uint32_t)ks * 32);
}
__device__ __forceinline__ void mma_frag(float acc[2][4][4], const Frag& f) {
#pragma unroll
    for (int mb = 0; mb < 2; mb++)
#pragma unroll
        for (int nbp = 0; nbp < 2; nbp++) {
            mma_bf16(acc[mb][2 * nbp],     f.a[mb], f.b[nbp][0], f.b[nbp][2]);
            mma_bf16(acc[mb][2 * nbp + 1], f.a[mb], f.b[nbp][1], f.b[nbp][3]);
        }
}

// ===================== persistent fused main kernel =====================
// 148 CTAs x 512 thr (16 warps: wm 0..1 x wn 0..7), warp tile 32x32.
// Static schedule over 4096 tiles of 64 px; one __syncthreads per tile.
// Fragment-level software pipeline: ldsm for kstep+1 issued before mma of kstep.
__global__ void __launch_bounds__(NTHR, 1)
pcl_main(const float* __restrict__ feats, const float* __restrict__ queue,
         const int* __restrict__ labels)
{
    extern __shared__ char smem[];
    const uint32_t sb = smem_u32(smem);
    const int tid = threadIdx.x, lane = tid & 31, wid = tid >> 5;
    const int wm = wid >> 3, wn = wid & 7;
    const int bid = blockIdx.x;

    // ---- stage B once: queue fp32 -> bf16 [n][k] ----
    for (int i = tid; i < 256 * 128; i += NTHR) {
        int n = i >> 7, k2 = i & 127;
        float2 v = *(const float2*)(queue + n * 256 + k2 * 2);
        *(__nv_bfloat162*)(smem + OFF_B + n * B_STRIDE + k2 * 4) =
            __floats2bfloat162_rn(v.x, v.y);
    }
    // ---- stage first tile (buf 0) ----
    {
        const int n0 = bid * TILE_P;
        const float* fp = feats + (size_t)(n0 / HW) * CD * HW + (n0 % HW);
        for (int i = tid; i < 256 * 32; i += NTHR) {
            int row = i >> 5, p2 = i & 31;
            float2 v = *(const float2*)(fp + (size_t)row * HW + p2 * 2);
            *(__nv_bfloat162*)(smem + OFF_A + row * A_STRIDE + p2 * 4) =
                __floats2bfloat162_rn(v.x, v.y);
        }
        const int* lp = labels + (size_t)n0 * 256;
        for (int s = tid; s < 2048; s += NTHR) {
            int px = s >> 5, sub = s & 31;
            const int4* l4 = (const int4*)(lp + px * 256 + sub * 8);
            ((unsigned char*)(smem + OFF_LAB))[px * 32 + sub] =
                (unsigned char)mask8(l4[0], l4[1]);
        }
    }
    __syncthreads();

    // ldsm lane decomposition
    const int r8   = lane & 7;
    const int sel8 = (lane >> 3) & 1;
    const int selk = (lane >> 4) & 1;
    const uint32_t b_base = sb + OFF_B
        + (uint32_t)(wn * 32 + sel8 * 8 + r8) * B_STRIDE + (uint32_t)(selk * 8) * 2;
    const uint32_t a_lane_off =
        (uint32_t)(selk * 8 + r8) * A_STRIDE + (uint32_t)(wm * 32 + sel8 * 8) * 2;

    int p = 0;  // buffer parity
#pragma unroll 1
    for (int cur = bid; cur < NTILES; cur += GRID, p ^= 1) {
        const int nxt = cur + GRID;
        const bool pf = nxt < NTILES;
        const uint32_t a_base = sb + OFF_A + (uint32_t)p * A_BUF + a_lane_off;
        char* anxt = smem + OFF_A + (p ^ 1) * A_BUF;
        unsigned char* lmnxt = (unsigned char*)(smem + OFF_LAB + (p ^ 1) * 2048);
        const float* fnx = nullptr; const int* lnx = nullptr;
        if (pf) {
            const int nn0 = nxt * TILE_P;
            fnx = feats + (size_t)(nn0 / HW) * CD * HW + (nn0 % HW);
            lnx = labels + (size_t)nn0 * 256;
        }

        float acc[2][4][4];
#pragma unroll
        for (int mb = 0; mb < 2; mb++)
#pragma unroll
            for (int nb = 0; nb < 4; nb++)
#pragma unroll
                for (int e = 0; e < 4; e++) acc[mb][nb][e] = 0.0f;

        Frag fr[2];
#pragma unroll
        for (int g = 0; g < 4; g++) {
            // issue prefetch LDGs for k-group g of tile nxt (latency hidden by mma)
            float4 pa0, pa1; int4 pl0, pl1;
            const int rowp = g * 64 + (tid >> 3);
            const int q = tid & 7;
            const int slot = g * 512 + tid, pxl = slot >> 5, sub = slot & 31;
            if (pf) {
                const float4* asrc = (const float4*)(fnx + (size_t)rowp * HW);
                pa0 = asrc[q]; pa1 = asrc[q + 8];
                const int4* lsrc = (const int4*)(lnx + pxl * 256 + sub * 8);
                pl0 = lsrc[0]; pl1 = lsrc[1];
            }
            // prime kstep g*4, then pipelined: ldsm(ks+1) before mma(ks)
            load_frag(fr[0], a_base, b_base, g * 4);
#pragma unroll
            for (int kk = 0; kk < 4; kk++) {
                if (kk < 3) load_frag(fr[(kk + 1) & 1], a_base, b_base, g * 4 + kk + 1);
                mma_frag(acc, fr[kk & 1]);
            }
            // drain prefetch into nxt buffers
            if (pf) {
                __nv_bfloat162 lo0 = __floats2bfloat162_rn(pa0.x, pa0.y);
                __nv_bfloat162 hi0 = __floats2bfloat162_rn(pa0.z, pa0.w);
                uint2 v0 = { *(uint32_t*)&lo0, *(uint32_t*)&hi0 };
                *(uint2*)(anxt + rowp * A_STRIDE + q * 8) = v0;
                __nv_bfloat162 lo1 = __floats2bfloat162_rn(pa1.x, pa1.y);
                __nv_bfloat162 hi1 = __floats2bfloat162_rn(pa1.z, pa1.w);
                uint2 v1 = { *(uint32_t*)&lo1, *(uint32_t*)&hi1 };
                *(uint2*)(anxt + rowp * A_STRIDE + (q + 8) * 8) = v1;
                lmnxt[pxl * 32 + sub] = (unsigned char)mask8(pl0, pl1);
            }
        }

        // ---- epilogue tile cur: warp-local, no smem writes, no barrier ----
        const unsigned* labm = (const unsigned*)(smem + OFF_LAB + p * 2048);
        // hoist the 4 mask words (one per (mb,half) row) before the math
        unsigned mwv[2][2];
#pragma unroll
        for (int mb = 0; mb < 2; mb++)
#pragma unroll
            for (int half = 0; half < 2; half++) {
                const int row = wm * 32 + mb * 16 + (lane >> 2) + half * 8;
                mwv[mb][half] = labm[row * 8 + wn];
            }
#pragma unroll
        for (int mb = 0; mb < 2; mb++) {
#pragma unroll
            for (int half = 0; half < 2; half++) {
                const int row = wm * 32 + mb * 16 + (lane >> 2) + half * 8;
                const unsigned mw = mwv[mb][half];
                float en = 0.0f, ep = 0.0f;
#pragma unroll
                for (int nb = 0; nb < 4; nb++) {
                    const int bit0 = nb * 8 + (lane & 3) * 2;
                    float l0 = acc[mb][nb][half * 2]     * INV_T;
                    float l1 = acc[mb][nb][half * 2 + 1] * INV_T;
                    bool y0 = (mw >> bit0) & 1u;
                    bool y1 = (mw >> (bit0 + 1)) & 1u;
                    float e0 = __expf(y0 ? -l0 : l0);
                    float e1 = __expf(y1 ? -l1 : l1);
                    en += y0 ? 0.0f : e0;  ep += y0 ? e0 : 0.0f;
                    en += y1 ? 0.0f : e1;  ep += y1 ? e1 : 0.0f;
                }
                en += __shfl_xor_sync(0xffffffffu, en, 1);
                en += __shfl_xor_sync(0xffffffffu, en, 2);
                ep += __shfl_xor_sync(0xffffffffu, ep, 1);
                ep += __shfl_xor_sync(0xffffffffu, ep, 2);
                if ((lane & 3) == 0) {   // deterministic per-(tile,wn,row) slots
                    const int slot = cur * 512 + wn * 64 + row;
                    g_en[slot] = en;
                    g_ep[slot] = ep;
                }
            }
        }
        __syncthreads();   // flip double buffers
    }
}

// ===================== finalize 1: combine wn partials, per-block reduce =====
__global__ void __launch_bounds__(512) pcl_fin1()
{
    __shared__ float ss[16];
    __shared__ int   sc[16];
    const int n = blockIdx.x * 512 + threadIdx.x;   // pixel id
    const int tile = n >> 6, row = n & 63;
    const int base = tile * 512 + row;
    float en = 0.0f, ep = 0.0f;
#pragma unroll
    for (int w = 0; w < 8; w++) {
        en += g_en[base + w * 64];
        ep += g_ep[base + w * 64];
    }
    float loss = __logf(en * ep + 1.0f);
    int   cnt  = (loss != 0.0f) ? 1 : 0;
#pragma unroll
    for (int off = 16; off > 0; off >>= 1) {
        loss += __shfl_xor_sync(0xffffffffu, loss, off);
        cnt  += __shfl_xor_sync(0xffffffffu, cnt,  off);
    }
    const int lane = threadIdx.x & 31, wid = threadIdx.x >> 5;
    if (lane == 0) { ss[wid] = loss; sc[wid] = cnt; }
    __syncthreads();
    if (threadIdx.x == 0) {
        float s = 0.0f; int c = 0;
#pragma unroll
        for (int w = 0; w < 16; w++) { s += ss[w]; c += sc[w]; }
        g_partial[blockIdx.x] = s;
        g_pcnt[blockIdx.x]    = c;
    }
}

// ===================== finalize 2: scalar =====================
__global__ void __launch_bounds__(512) pcl_fin2(float* __restrict__ out)
{
    __shared__ float ss[16];
    __shared__ int   sc[16];
    float s = g_partial[threadIdx.x];
    int   c = g_pcnt[threadIdx.x];
#pragma unroll
    for (int off = 16; off > 0; off >>= 1) {
        s += __shfl_xor_sync(0xffffffffu, s, off);
        c += __shfl_xor_sync(0xffffffffu, c, off);
    }
    const int lane = threadIdx.x & 31, wid = threadIdx.x >> 5;
    if (lane == 0) { ss[wid] = s; sc[wid] = c; }
    __syncthreads();
    if (threadIdx.x == 0) {
        float t = 0.0f; int c2 = 0;
#pragma unroll
        for (int w = 0; w < 16; w++) { t += ss[w]; c2 += sc[w]; }
        out[0] = (c2 == 0) ? 0.0f : t / (float)(c2 < 1 ? 1 : c2);
    }
}

extern "C" void kernel_launch(void* const* d_in, const int* in_sizes, int n_in,
                              void* d_out, int out_size)
{
    const float* feats  = (const float*)d_in[0];
    const float* queue  = (const float*)d_in[1];
    const int*   labels = (const int*)d_in[2];
    float* out = (float*)d_out;

    static bool attr_set = false;
    if (!attr_set) {
        cudaFuncSetAttribute(pcl_main,
                             cudaFuncAttributeMaxDynamicSharedMemorySize, SMEM_SZ);
        attr_set = true;
    }

    pcl_main<<<GRID, NTHR, SMEM_SZ>>>(feats, queue, labels);
    pcl_fin1<<<FIN_BLKS, 512>>>();
    pcl_fin2<<<1, 512>>>(out);
}

// round 12
// speedup vs baseline: 1.0231x; 1.0231x over previous
#include <cuda_runtime.h>
#include <cuda_bf16.h>
#include <cstdint>

#define NPIX   262144
#define CD     256
#define HW     16384
#define TILE_P 64
#define NTILES (NPIX / TILE_P)      // 4096
#define GRID   148
#define NTHR   512
// queue prescale: (1/T) * log2(e)  -> epilogue uses ex2 directly
#define QSCALE 20.60992915555662f

// smem layout (bytes)
#define B_STRIDE 528                  // 132 words = 4 mod 32 banks: conflict-free ldsm
#define A_STRIDE 144                  // 36 words  = 4 mod 32 banks
#define A_BUF    (256 * A_STRIDE)     // 36864
#define OFF_B    0
#define OFF_A    (256 * B_STRIDE)     // 135168
#define OFF_LAB  (OFF_A + 2 * A_BUF)  // 208896 : 2 x (64 px * 32 bytes)
#define SMEM_SZ  (OFF_LAB + 2 * 2048) // 212992

#define FIN_BLKS 512

__device__ float g_en[NTILES * 512];     // [tile][wn 0..7][row 0..63]  8MB
__device__ float g_ep[NTILES * 512];     // 8MB
__device__ float g_partial[FIN_BLKS];
__device__ int   g_pcnt[FIN_BLKS];

__device__ __forceinline__ uint32_t smem_u32(const void* p) {
    uint32_t a;
    asm("{ .reg .u64 t; cvta.to.shared.u64 t, %1; cvt.u32.u64 %0, t; }" : "=r"(a) : "l"(p));
    return a;
}
__device__ __forceinline__ void ldsm_x4(uint32_t* r, uint32_t addr) {
    asm volatile("ldmatrix.sync.aligned.m8n8.x4.shared.b16 {%0,%1,%2,%3}, [%4];"
                 : "=r"(r[0]), "=r"(r[1]), "=r"(r[2]), "=r"(r[3]) : "r"(addr));
}
__device__ __forceinline__ void ldsm_x4_t(uint32_t* r, uint32_t addr) {
    asm volatile("ldmatrix.sync.aligned.m8n8.x4.trans.shared.b16 {%0,%1,%2,%3}, [%4];"
                 : "=r"(r[0]), "=r"(r[1]), "=r"(r[2]), "=r"(r[3]) : "r"(addr));
}
__device__ __forceinline__ void mma_bf16(float* d, const uint32_t* a,
                                         uint32_t b0, uint32_t b1) {
    asm volatile(
        "mma.sync.aligned.m16n8k16.row.col.f32.bf16.bf16.f32 "
        "{%0,%1,%2,%3}, {%4,%5,%6,%7}, {%8,%9}, {%0,%1,%2,%3};"
        : "+f"(d[0]), "+f"(d[1]), "+f"(d[2]), "+f"(d[3])
        : "r"(a[0]), "r"(a[1]), "r"(a[2]), "r"(a[3]), "r"(b0), "r"(b1));
}
__device__ __forceinline__ float ex2(float x) {
    float r;
    asm("ex2.approx.f32 %0, %1;" : "=f"(r) : "f"(x));
    return r;
}
__device__ __forceinline__ unsigned mask8(const int4& v0, const int4& v1) {
    unsigned m = 0;
    m |= (v0.x != 0 ? 1u : 0u);
    m |= (v0.y != 0 ? 2u : 0u);
    m |= (v0.z != 0 ? 4u : 0u);
    m |= (v0.w != 0 ? 8u : 0u);
    m |= (v1.x != 0 ? 16u : 0u);
    m |= (v1.y != 0 ? 32u : 0u);
    m |= (v1.z != 0 ? 64u : 0u);
    m |= (v1.w != 0 ? 128u : 0u);
    return m;
}

// ===================== persistent fused main kernel =====================
// 148 CTAs x 512 thr (16 warps: wm 0..1 x wn 0..7), warp tile 32x32.
// Static schedule over 4096 tiles of 64 px; one __syncthreads per tile.
// L2 prefetch of tile cur+2*GRID issued at tile top (hides DRAM latency of
// the LDG prefetch that runs one tile later).
__global__ void __launch_bounds__(NTHR, 1)
pcl_main(const float* __restrict__ feats, const float* __restrict__ queue,
         const int* __restrict__ labels)
{
    extern __shared__ char smem[];
    const uint32_t sb = smem_u32(smem);
    const int tid = threadIdx.x, lane = tid & 31, wid = tid >> 5;
    const int wm = wid >> 3, wn = wid & 7;
    const int bid = blockIdx.x;

    // ---- stage B once: queue fp32 -> bf16 [n][k], prescaled by QSCALE ----
    for (int i = tid; i < 256 * 128; i += NTHR) {
        int n = i >> 7, k2 = i & 127;
        float2 v = *(const float2*)(queue + n * 256 + k2 * 2);
        *(__nv_bfloat162*)(smem + OFF_B + n * B_STRIDE + k2 * 4) =
            __floats2bfloat162_rn(v.x * QSCALE, v.y * QSCALE);
    }
    // ---- stage first tile (buf 0) ----
    {
        const int n0 = bid * TILE_P;
        const float* fp = feats + (size_t)(n0 / HW) * CD * HW + (n0 % HW);
        for (int i = tid; i < 256 * 32; i += NTHR) {
            int row = i >> 5, p2 = i & 31;
            float2 v = *(const float2*)(fp + (size_t)row * HW + p2 * 2);
            *(__nv_bfloat162*)(smem + OFF_A + row * A_STRIDE + p2 * 4) =
                __floats2bfloat162_rn(v.x, v.y);
        }
        const int* lp = labels + (size_t)n0 * 256;
        for (int s = tid; s < 2048; s += NTHR) {
            int px = s >> 5, sub = s & 31;
            const int4* l4 = (const int4*)(lp + px * 256 + sub * 8);
            ((unsigned char*)(smem + OFF_LAB))[px * 32 + sub] =
                (unsigned char)mask8(l4[0], l4[1]);
        }
    }
    __syncthreads();

    // ldsm lane decomposition
    const int r8   = lane & 7;
    const int sel8 = (lane >> 3) & 1;
    const int selk = (lane >> 4) & 1;
    const uint32_t b_base = sb + OFF_B
        + (uint32_t)(wn * 32 + sel8 * 8 + r8) * B_STRIDE + (uint32_t)(selk * 8) * 2;
    const uint32_t a_lane_off =
        (uint32_t)(selk * 8 + r8) * A_STRIDE + (uint32_t)(wm * 32 + sel8 * 8) * 2;

    int p = 0;  // buffer parity
#pragma unroll 1
    for (int cur = bid; cur < NTILES; cur += GRID, p ^= 1) {
        const int nxt = cur + GRID;
        const bool pf = nxt < NTILES;
        const uint32_t a_base = sb + OFF_A + (uint32_t)p * A_BUF + a_lane_off;
        char* anxt = smem + OFF_A + (p ^ 1) * A_BUF;
        unsigned char* lmnxt = (unsigned char*)(smem + OFF_LAB + (p ^ 1) * 2048);
        const float* fnx = nullptr; const int* lnx = nullptr;
        if (pf) {
            const int nn0 = nxt * TILE_P;
            fnx = feats + (size_t)(nn0 / HW) * CD * HW + (nn0 % HW);
            lnx = labels + (size_t)nn0 * 256;
        }

        // ---- L2 prefetch of tile cur + 2*GRID (consumed one tile later) ----
        {
            const int nn2 = cur + 2 * GRID;
            if (nn2 < NTILES) {
                const int m0 = nn2 * TILE_P;
                const float* fp2 = feats + (size_t)(m0 / HW) * CD * HW + (m0 % HW);
                const int*   lp2 = labels + (size_t)m0 * 256;
                // A: 256 channel rows x 256B (2 lines each) -> 512 lines
                const char* a0 = (const char*)(fp2 + (size_t)(tid >> 1) * HW)
                                 + (tid & 1) * 128;
                asm volatile("prefetch.global.L2 [%0];" :: "l"(a0));
                // labels: 64 px x 1KB (8 lines each) -> 512 lines
                const char* l0 = (const char*)(lp2 + (tid >> 3) * 256 + (tid & 7) * 32);
                asm volatile("prefetch.global.L2 [%0];" :: "l"(l0));
            }
        }

        float acc[2][4][4];
#pragma unroll
        for (int mb = 0; mb < 2; mb++)
#pragma unroll
            for (int nb = 0; nb < 4; nb++)
#pragma unroll
                for (int e = 0; e < 4; e++) acc[mb][nb][e] = 0.0f;

#pragma unroll
        for (int g = 0; g < 4; g++) {
            // prefetch tile nxt: A rows [g*64, g*64+64), label slots [g*512, g*512+512)
            float4 pa0, pa1; int4 pl0, pl1;
            const int rowp = g * 64 + (tid >> 3);
            const int q = tid & 7;
            const int slot = g * 512 + tid, pxl = slot >> 5, sub = slot & 31;
            if (pf) {
                const float4* asrc = (const float4*)(fnx + (size_t)rowp * HW);
                pa0 = asrc[q]; pa1 = asrc[q + 8];
                const int4* lsrc = (const int4*)(lnx + pxl * 256 + sub * 8);
                pl0 = lsrc[0]; pl1 = lsrc[1];
            }
            // 4 ksteps of mma on tile cur (k-group g)
#pragma unroll
            for (int kk = 0; kk < 4; kk++) {
                const int ks = g * 4 + kk;
                uint32_t a[2][4], bq[2][4];
                ldsm_x4_t(a[0], a_base + (uint32_t)ks * 16 * A_STRIDE);
                ldsm_x4_t(a[1], a_base + (uint32_t)ks * 16 * A_STRIDE + 32);
                ldsm_x4(bq[0], b_base + (uint32_t)ks * 32);
                ldsm_x4(bq[1], b_base + 16 * B_STRIDE + (uint32_t)ks * 32);
#pragma unroll
                for (int mb = 0; mb < 2; mb++)
#pragma unroll
                    for (int nbp = 0; nbp < 2; nbp++) {
                        mma_bf16(acc[mb][2 * nbp],     a[mb], bq[nbp][0], bq[nbp][2]);
                        mma_bf16(acc[mb][2 * nbp + 1], a[mb], bq[nbp][1], bq[nbp][3]);
                    }
            }
            // drain prefetch into nxt buffers
            if (pf) {
                __nv_bfloat162 lo0 = __floats2bfloat162_rn(pa0.x, pa0.y);
                __nv_bfloat162 hi0 = __floats2bfloat162_rn(pa0.z, pa0.w);
                uint2 v0 = { *(uint32_t*)&lo0, *(uint32_t*)&hi0 };
                *(uint2*)(anxt + rowp * A_STRIDE + q * 8) = v0;
                __nv_bfloat162 lo1 = __floats2bfloat162_rn(pa1.x, pa1.y);
                __nv_bfloat162 hi1 = __floats2bfloat162_rn(pa1.z, pa1.w);
                uint2 v1 = { *(uint32_t*)&lo1, *(uint32_t*)&hi1 };
                *(uint2*)(anxt + rowp * A_STRIDE + (q + 8) * 8) = v1;
                lmnxt[pxl * 32 + sub] = (unsigned char)mask8(pl0, pl1);
            }
        }

        // ---- epilogue tile cur: acc already in log2 scale -> raw ex2 ----
        const unsigned* labm = (const unsigned*)(smem + OFF_LAB + p * 2048);
#pragma unroll
        for (int mb = 0; mb < 2; mb++) {
#pragma unroll
            for (int half = 0; half < 2; half++) {
                const int row = wm * 32 + mb * 16 + (lane >> 2) + half * 8;
                const unsigned mw = labm[row * 8 + wn];   // 32 classes of this warp
                float en = 0.0f, ep = 0.0f;
#pragma unroll
                for (int nb = 0; nb < 4; nb++) {
                    const int bit0 = nb * 8 + (lane & 3) * 2;
                    float l0 = acc[mb][nb][half * 2];
                    float l1 = acc[mb][nb][half * 2 + 1];
                    bool y0 = (mw >> bit0) & 1u;
                    bool y1 = (mw >> (bit0 + 1)) & 1u;
                    float e0 = ex2(y0 ? -l0 : l0);
                    float e1 = ex2(y1 ? -l1 : l1);
                    en += y0 ? 0.0f : e0;  ep += y0 ? e0 : 0.0f;
                    en += y1 ? 0.0f : e1;  ep += y1 ? e1 : 0.0f;
                }
                en += __shfl_xor_sync(0xffffffffu, en, 1);
                en += __shfl_xor_sync(0xffffffffu, en, 2);
                ep += __shfl_xor_sync(0xffffffffu, ep, 1);
                ep += __shfl_xor_sync(0xffffffffu, ep, 2);
                if ((lane & 3) == 0) {   // deterministic per-(tile,wn,row) slots
                    const int slot = cur * 512 + wn * 64 + row;
                    g_en[slot] = en;
                    g_ep[slot] = ep;
                }
            }
        }
        __syncthreads();   // flip double buffers
    }
}

// ===================== finalize 1: combine wn partials, per-block reduce =====
__global__ void __launch_bounds__(512) pcl_fin1()
{
    __shared__ float ss[16];
    __shared__ int   sc[16];
    const int n = blockIdx.x * 512 + threadIdx.x;   // pixel id
    const int tile = n >> 6, row = n & 63;
    const int base = tile * 512 + row;
    float en = 0.0f, ep = 0.0f;
#pragma unroll
    for (int w = 0; w < 8; w++) {
        en += g_en[base + w * 64];
        ep += g_ep[base + w * 64];
    }
    float loss = __logf(en * ep + 1.0f);
    int   cnt  = (loss != 0.0f) ? 1 : 0;
#pragma unroll
    for (int off = 16; off > 0; off >>= 1) {
        loss += __shfl_xor_sync(0xffffffffu, loss, off);
        cnt  += __shfl_xor_sync(0xffffffffu, cnt,  off);
    }
    const int lane = threadIdx.x & 31, wid = threadIdx.x >> 5;
    if (lane == 0) { ss[wid] = loss; sc[wid] = cnt; }
    __syncthreads();
    if (threadIdx.x == 0) {
        float s = 0.0f; int c = 0;
#pragma unroll
        for (int w = 0; w < 16; w++) { s += ss[w]; c += sc[w]; }
        g_partial[blockIdx.x] = s;
        g_pcnt[blockIdx.x]    = c;
    }
}

// ===================== finalize 2: scalar =====================
__global__ void __launch_bounds__(512) pcl_fin2(float* __restrict__ out)
{
    __shared__ float ss[16];
    __shared__ int   sc[16];
    float s = g_partial[threadIdx.x];
    int   c = g_pcnt[threadIdx.x];
#pragma unroll
    for (int off = 16; off > 0; off >>= 1) {
        s += __shfl_xor_sync(0xffffffffu, s, off);
        c += __shfl_xor_sync(0xffffffffu, c, off);
    }
    const int lane = threadIdx.x & 31, wid = threadIdx.x >> 5;
    if (lane == 0) { ss[wid] = s; sc[wid] = c; }
    __syncthreads();
    if (threadIdx.x == 0) {
        float t = 0.0f; int c2 = 0;
#pragma unroll
        for (int w = 0; w < 16; w++) { t += ss[w]; c2 += sc[w]; }
        out[0] = (c2 == 0) ? 0.0f : t / (float)(c2 < 1 ? 1 : c2);
    }
}

extern "C" void kernel_launch(void* const* d_in, const int* in_sizes, int n_in,
                              void* d_out, int out_size)
{
    const float* feats  = (const float*)d_in[0];
    const float* queue  = (const float*)d_in[1];
    const int*   labels = (const int*)d_in[2];
    float* out = (float*)d_out;

    static bool attr_set = false;
    if (!attr_set) {
        cudaFuncSetAttribute(pcl_main,
                             cudaFuncAttributeMaxDynamicSharedMemorySize, SMEM_SZ);
        attr_set = true;
    }

    pcl_main<<<GRID, NTHR, SMEM_SZ>>>(feats, queue, labels);
    pcl_fin1<<<FIN_BLKS, 512>>>();
    pcl_fin2<<<1, 512>>>(out);
}

// round 13
// speedup vs baseline: 1.0233x; 1.0002x over previous
#include <cuda_runtime.h>
#include <cuda_bf16.h>
#include <cstdint>

#define NPIX   262144
#define CD     256
#define HW     16384
#define TILE_P 32
#define NTILES (NPIX / TILE_P)      // 8192 tiles of 32 px
#define GRID   148
#define NTHR   512                  // 2 domains x 256
#define NDOM_G (GRID * 2)           // 296 global domains
// queue prescale: (1/T) * log2(e)  -> epilogue uses ex2 directly
#define QSCALE 20.60992915555662f

// smem layout (bytes)
#define B_STRIDE 528                  // 132 words = 4 mod 32 banks: conflict-free ldsm
#define A_STRIDE 80                   // 20 words  = 5 mod 8 chunks: conflict-free ldsm
#define A_BUF    (256 * A_STRIDE)     // 20480 per buffer
#define OFF_B    0                    // 256*528 = 135168
#define OFF_A    135168               // 4 buffers (dom,parity) -> +81920
#define OFF_LAB  (OFF_A + 4 * A_BUF)  // 217088 : 4 x 1024 (32 px * 32 bytes)
#define SMEM_SZ  (OFF_LAB + 4 * 1024 + 64)   // 221248

#define FIN_BLKS 512

__device__ float g_en[NTILES * 256];     // [tile][wn 0..7][row 0..31]  8MB
__device__ float g_ep[NTILES * 256];     // 8MB
__device__ float g_partial[FIN_BLKS];
__device__ int   g_pcnt[FIN_BLKS];

__device__ __forceinline__ uint32_t smem_u32(const void* p) {
    uint32_t a;
    asm("{ .reg .u64 t; cvta.to.shared.u64 t, %1; cvt.u32.u64 %0, t; }" : "=r"(a) : "l"(p));
    return a;
}
__device__ __forceinline__ void ldsm_x4(uint32_t* r, uint32_t addr) {
    asm volatile("ldmatrix.sync.aligned.m8n8.x4.shared.b16 {%0,%1,%2,%3}, [%4];"
                 : "=r"(r[0]), "=r"(r[1]), "=r"(r[2]), "=r"(r[3]) : "r"(addr));
}
__device__ __forceinline__ void ldsm_x4_t(uint32_t* r, uint32_t addr) {
    asm volatile("ldmatrix.sync.aligned.m8n8.x4.trans.shared.b16 {%0,%1,%2,%3}, [%4];"
                 : "=r"(r[0]), "=r"(r[1]), "=r"(r[2]), "=r"(r[3]) : "r"(addr));
}
__device__ __forceinline__ void mma_bf16(float* d, const uint32_t* a,
                                         uint32_t b0, uint32_t b1) {
    asm volatile(
        "mma.sync.aligned.m16n8k16.row.col.f32.bf16.bf16.f32 "
        "{%0,%1,%2,%3}, {%4,%5,%6,%7}, {%8,%9}, {%0,%1,%2,%3};"
        : "+f"(d[0]), "+f"(d[1]), "+f"(d[2]), "+f"(d[3])
        : "r"(a[0]), "r"(a[1]), "r"(a[2]), "r"(a[3]), "r"(b0), "r"(b1));
}
__device__ __forceinline__ float ex2(float x) {
    float r;
    asm("ex2.approx.f32 %0, %1;" : "=f"(r) : "f"(x));
    return r;
}
__device__ __forceinline__ unsigned mask8(const int4& v0, const int4& v1) {
    unsigned m = 0;
    m |= (v0.x != 0 ? 1u : 0u);
    m |= (v0.y != 0 ? 2u : 0u);
    m |= (v0.z != 0 ? 4u : 0u);
    m |= (v0.w != 0 ? 8u : 0u);
    m |= (v1.x != 0 ? 16u : 0u);
    m |= (v1.y != 0 ? 32u : 0u);
    m |= (v1.z != 0 ? 64u : 0u);
    m |= (v1.w != 0 ? 128u : 0u);
    return m;
}

// ===================== persistent fused main kernel =====================
// 148 CTAs x 512 thr = 2 INDEPENDENT domains of 256 thr (8 warps, warp tile
// 32x32, warp grid 1x8 over a 32px x 256cls tile). Queue shared read-only.
// Each domain: private A/label double buffers + private named barrier; the
// domains drift out of phase and fill each other's pipeline stalls.
__global__ void __launch_bounds__(NTHR, 1)
pcl_main(const float* __restrict__ feats, const float* __restrict__ queue,
         const int* __restrict__ labels)
{
    extern __shared__ char smem[];
    const uint32_t sb = smem_u32(smem);
    const int tid = threadIdx.x, lane = tid & 31;
    const int dom = tid >> 8;            // 0..1
    const int dtid = tid & 255;          // thread within domain
    const int wn = dtid >> 5;            // 0..7 : class column of this warp
    const int gd = blockIdx.x * 2 + dom; // global domain id 0..295

    // ---- stage B once (whole block): queue fp32 -> bf16, prescaled ----
    for (int i = tid; i < 256 * 128; i += NTHR) {
        int n = i >> 7, k2 = i & 127;
        float2 v = *(const float2*)(queue + n * 256 + k2 * 2);
        *(__nv_bfloat162*)(smem + OFF_B + n * B_STRIDE + k2 * 4) =
            __floats2bfloat162_rn(v.x * QSCALE, v.y * QSCALE);
    }
    // ---- stage first tile (per domain, buffer parity 0) ----
    {
        const int n0 = gd * TILE_P;
        const float* fp = feats + (size_t)(n0 / HW) * CD * HW + (n0 % HW);
        char* a0 = smem + OFF_A + (dom * 2) * A_BUF;
        for (int i = dtid; i < 256 * 16; i += 256) {
            int row = i >> 4, p2 = i & 15;
            float2 v = *(const float2*)(fp + (size_t)row * HW + p2 * 2);
            *(__nv_bfloat162*)(a0 + row * A_STRIDE + p2 * 4) =
                __floats2bfloat162_rn(v.x, v.y);
        }
        const int* lp = labels + (size_t)n0 * 256;
        unsigned char* lm0 = (unsigned char*)(smem + OFF_LAB + (dom * 2) * 1024);
        for (int s = dtid; s < 1024; s += 256) {
            int px = s >> 5, sub = s & 31;
            const int4* l4 = (const int4*)(lp + px * 256 + sub * 8);
            lm0[px * 32 + sub] = (unsigned char)mask8(l4[0], l4[1]);
        }
    }
    __syncthreads();   // B + both domains' first tiles visible

    // ldsm lane decomposition
    const int r8   = lane & 7;
    const int sel8 = (lane >> 3) & 1;
    const int selk = (lane >> 4) & 1;
    const uint32_t b_base = sb + OFF_B
        + (uint32_t)(wn * 32 + sel8 * 8 + r8) * B_STRIDE + (uint32_t)selk * 16;
    const uint32_t a_lane_off =
        (uint32_t)(selk * 8 + r8) * A_STRIDE + (uint32_t)sel8 * 16;

    int p = 0;  // buffer parity (per domain)
#pragma unroll 1
    for (int cur = gd; cur < NTILES; cur += NDOM_G, p ^= 1) {
        const int nxt = cur + NDOM_G;
        const bool pf = nxt < NTILES;
        const uint32_t a_base = sb + OFF_A + (uint32_t)(dom * 2 + p) * A_BUF + a_lane_off;
        char* anxt = smem + OFF_A + (dom * 2 + (p ^ 1)) * A_BUF;
        unsigned char* lmnxt = (unsigned char*)(smem + OFF_LAB + (dom * 2 + (p ^ 1)) * 1024);
        const float* fnx = nullptr; const int* lnx = nullptr;
        if (pf) {
            const int nn0 = nxt * TILE_P;
            fnx = feats + (size_t)(nn0 / HW) * CD * HW + (nn0 % HW);
            lnx = labels + (size_t)nn0 * 256;
        }

        float acc[2][4][4];
#pragma unroll
        for (int mb = 0; mb < 2; mb++)
#pragma unroll
            for (int nb = 0; nb < 4; nb++)
#pragma unroll
                for (int e = 0; e < 4; e++) acc[mb][nb][e] = 0.0f;

#pragma unroll
        for (int g = 0; g < 4; g++) {
            // prefetch tile nxt: A rows [g*64, g*64+64), label slots [g*256, +256)
            float4 pa0, pa1; int4 pl0, pl1;
            const int rowp = g * 64 + (dtid >> 2);
            const int q4 = dtid & 3;
            const int slot = g * 256 + dtid, pxl = slot >> 5, sub = slot & 31;
            if (pf) {
                const float4* asrc = (const float4*)(fnx + (size_t)rowp * HW);
                pa0 = asrc[q4]; pa1 = asrc[q4 + 4];
                const int4* lsrc = (const int4*)(lnx + pxl * 256 + sub * 8);
                pl0 = lsrc[0]; pl1 = lsrc[1];
            }
            // 4 ksteps of mma on tile cur (k-group g)
#pragma unroll
            for (int kk = 0; kk < 4; kk++) {
                const int ks = g * 4 + kk;
                uint32_t a[2][4], bq[2][4];
                ldsm_x4_t(a[0], a_base + (uint32_t)ks * 16 * A_STRIDE);
                ldsm_x4_t(a[1], a_base + (uint32_t)ks * 16 * A_STRIDE + 32);
                ldsm_x4(bq[0], b_base + (uint32_t)ks * 32);
                ldsm_x4(bq[1], b_base + 16 * B_STRIDE + (uint32_t)ks * 32);
#pragma unroll
                for (int mb = 0; mb < 2; mb++)
#pragma unroll
                    for (int nbp = 0; nbp < 2; nbp++) {
                        mma_bf16(acc[mb][2 * nbp],     a[mb], bq[nbp][0], bq[nbp][2]);
                        mma_bf16(acc[mb][2 * nbp + 1], a[mb], bq[nbp][1], bq[nbp][3]);
                    }
            }
            // drain prefetch into nxt buffers
            if (pf) {
                __nv_bfloat162 lo0 = __floats2bfloat162_rn(pa0.x, pa0.y);
                __nv_bfloat162 hi0 = __floats2bfloat162_rn(pa0.z, pa0.w);
                uint2 v0 = { *(uint32_t*)&lo0, *(uint32_t*)&hi0 };
                *(uint2*)(anxt + rowp * A_STRIDE + q4 * 8) = v0;
                __nv_bfloat162 lo1 = __floats2bfloat162_rn(pa1.x, pa1.y);
                __nv_bfloat162 hi1 = __floats2bfloat162_rn(pa1.z, pa1.w);
                uint2 v1 = { *(uint32_t*)&lo1, *(uint32_t*)&hi1 };
                *(uint2*)(anxt + rowp * A_STRIDE + (q4 + 4) * 8) = v1;
                lmnxt[pxl * 32 + sub] = (unsigned char)mask8(pl0, pl1);
            }
        }

        // ---- epilogue tile cur: acc in log2 scale -> raw ex2; no barrier ----
        const unsigned* labm = (const unsigned*)(smem + OFF_LAB + (dom * 2 + p) * 1024);
#pragma unroll
        for (int mb = 0; mb < 2; mb++) {
#pragma unroll
            for (int half = 0; half < 2; half++) {
                const int row = mb * 16 + (lane >> 2) + half * 8;   // 0..31
                const unsigned mw = labm[row * 8 + wn];
                float en = 0.0f, ep = 0.0f;
#pragma unroll
                for (int nb = 0; nb < 4; nb++) {
                    const int bit0 = nb * 8 + (lane & 3) * 2;
                    float l0 = acc[mb][nb][half * 2];
                    float l1 = acc[mb][nb][half * 2 + 1];
                    bool y0 = (mw >> bit0) & 1u;
                    bool y1 = (mw >> (bit0 + 1)) & 1u;
                    float e0 = ex2(y0 ? -l0 : l0);
                    float e1 = ex2(y1 ? -l1 : l1);
                    en += y0 ? 0.0f : e0;  ep += y0 ? e0 : 0.0f;
                    en += y1 ? 0.0f : e1;  ep += y1 ? e1 : 0.0f;
                }
                en += __shfl_xor_sync(0xffffffffu, en, 1);
                en += __shfl_xor_sync(0xffffffffu, en, 2);
                ep += __shfl_xor_sync(0xffffffffu, ep, 1);
                ep += __shfl_xor_sync(0xffffffffu, ep, 2);
                if ((lane & 3) == 0) {   // deterministic per-(tile,wn,row) slots
                    const int slot = cur * 256 + wn * 32 + row;
                    g_en[slot] = en;
                    g_ep[slot] = ep;
                }
            }
        }
        // domain-private barrier: flip this domain's double buffers only
        asm volatile("bar.sync %0, 256;" :: "r"(dom + 1) : "memory");
    }
}

// ===================== finalize 1: combine wn partials, per-block reduce =====
__global__ void __launch_bounds__(512) pcl_fin1()
{
    __shared__ float ss[16];
    __shared__ int   sc[16];
    const int n = blockIdx.x * 512 + threadIdx.x;   // pixel id
    const int tile = n >> 5, row = n & 31;
    const int base = tile * 256 + row;
    float en = 0.0f, ep = 0.0f;
#pragma unroll
    for (int w = 0; w < 8; w++) {
        en += g_en[base + w * 32];
        ep += g_ep[base + w * 32];
    }
    float loss = __logf(en * ep + 1.0f);
    int   cnt  = (loss != 0.0f) ? 1 : 0;
#pragma unroll
    for (int off = 16; off > 0; off >>= 1) {
        loss += __shfl_xor_sync(0xffffffffu, loss, off);
        cnt  += __shfl_xor_sync(0xffffffffu, cnt,  off);
    }
    const int lane = threadIdx.x & 31, wid = threadIdx.x >> 5;
    if (lane == 0) { ss[wid] = loss; sc[wid] = cnt; }
    __syncthreads();
    if (threadIdx.x == 0) {
        float s = 0.0f; int c = 0;
#pragma unroll
        for (int w = 0; w < 16; w++) { s += ss[w]; c += sc[w]; }
        g_partial[blockIdx.x] = s;
        g_pcnt[blockIdx.x]    = c;
    }
}

// ===================== finalize 2: scalar =====================
__global__ void __launch_bounds__(512) pcl_fin2(float* __restrict__ out)
{
    __shared__ float ss[16];
    __shared__ int   sc[16];
    float s = g_partial[threadIdx.x];
    int   c = g_pcnt[threadIdx.x];
#pragma unroll
    for (int off = 16; off > 0; off >>= 1) {
        s += __shfl_xor_sync(0xffffffffu, s, off);
        c += __shfl_xor_sync(0xffffffffu, c, off);
    }
    const int lane = threadIdx.x & 31, wid = threadIdx.x >> 5;
    if (lane == 0) { ss[wid] = s; sc[wid] = c; }
    __syncthreads();
    if (threadIdx.x == 0) {
        float t = 0.0f; int c2 = 0;
#pragma unroll
        for (int w = 0; w < 16; w++) { t += ss[w]; c2 += sc[w]; }
        out[0] = (c2 == 0) ? 0.0f : t / (float)(c2 < 1 ? 1 : c2);
    }
}

extern "C" void kernel_launch(void* const* d_in, const int* in_sizes, int n_in,
                              void* d_out, int out_size)
{
    const float* feats  = (const float*)d_in[0];
    const float* queue  = (const float*)d_in[1];
    const int*   labels = (const int*)d_in[2];
    float* out = (float*)d_out;

    static bool attr_set = false;
    if (!attr_set) {
        cudaFuncSetAttribute(pcl_main,
                             cudaFuncAttributeMaxDynamicSharedMemorySize, SMEM_SZ);
        attr_set = true;
    }

    pcl_main<<<GRID, NTHR, SMEM_SZ>>>(feats, queue, labels);
    pcl_fin1<<<FIN_BLKS, 512>>>();
    pcl_fin2<<<1, 512>>>(out);
}